// round 9
// baseline (speedup 1.0000x reference)
#include <cuda_runtime.h>

// y[o*48+p, n, m] = sum_i W0[p,i] * t4[o, (n-1)%56, m, i]
// t4[o, n', m, i] = sum_{j,k} xpad[o, j, n', m+k] * W1[j,k,i]  (pad 3 each side, width)
//
// 112 CTAs (one per (o, out-row n)), 512 threads.
// w1 transposed [i][jk] for sequential stage-2 reads; xs at offset +3 for LDS.64 windows.

#define NCH 12
#define WID 56
#define XSTRIDE 64          // xs row stride; x col c at xs[j*64 + 3 + c]; zeros [0,3) & [59,64)
#define KS 7
#define NI 9
#define NP 48
#define W1TS 88             // w1t row stride ([i][j*7+k]), 88*4 bytes = 16B-aligned rows
#define T4S 60              // t4 row stride ([i][m])
#define W0S 12              // padded w0 row stride
#define THREADS 512

__global__ __launch_bounds__(THREADS, 1)
void fused_sepconv_kernel(const float* __restrict__ x,
                          const float* __restrict__ W0,
                          const float* __restrict__ W1,
                          float* __restrict__ out) {
    __shared__ alignas(16) float xs[NCH * XSTRIDE];   // 768
    __shared__ alignas(16) float w1t[NI * W1TS];      // 792, transposed W1
    __shared__ alignas(16) float w0p[NP * W0S];       // 576 (cols 9..11 unused)
    __shared__ alignas(16) float t4s[NI * T4S];       // 540, [i][m]

    const int b = blockIdx.x;             // 0..111
    const int o = b / WID;
    const int n = b % WID;
    const int nin = (n + WID - 1) % WID;  // roll(+1) along height
    const int t = threadIdx.x;

    // ---- Phase 1: all global loads issued first (max MLP) ----
    // [0,168): x quads; [168,357): W1 quads (scatter-transpose); [357,501): W0 3 scalars
    float4 v = make_float4(0.f, 0.f, 0.f, 0.f);
    float w0v = 0.f, w0v2 = 0.f, w0v3 = 0.f;
    if (t < 168) {
        int j  = t / 14;
        int q4 = t % 14;
        v = *(const float4*)&x[(((o * NCH + j) * WID + nin) * WID) + 4 * q4];
    } else if (t < 357) {
        v = *(const float4*)&W1[4 * (t - 168)];
    } else if (t < 501) {
        w0v  = W0[t - 357];
        w0v2 = W0[t - 357 + 144];
        w0v3 = W0[t - 357 + 288];
    }

    // Scatter to shared
    if (t < 168) {
        int j  = t / 14;
        int q4 = t % 14;
        float* dst = &xs[j * XSTRIDE + 3 + 4 * q4];
        dst[0] = v.x; dst[1] = v.y; dst[2] = v.z; dst[3] = v.w;
        if (q4 == 0) {                     // left pad: xs idx 0..2
            xs[j * XSTRIDE + 0] = 0.f;
            xs[j * XSTRIDE + 1] = 0.f;
            xs[j * XSTRIDE + 2] = 0.f;
        } else if (q4 == 13) {             // right pad: xs idx 59..63
            #pragma unroll
            for (int z = 59; z < 64; ++z) xs[j * XSTRIDE + z] = 0.f;
        }
    } else if (t < 357) {
        int e = 4 * (t - 168);
        const float* sv = (const float*)&v;
        #pragma unroll
        for (int r = 0; r < 4; ++r) {
            int ee = e + r;                // W1 linear index = jk*9 + i
            w1t[(ee % NI) * W1TS + (ee / NI)] = sv[r];
        }
    } else if (t < 501) {
        int e0 = t - 357;
        int e1 = e0 + 144;
        int e2 = e0 + 288;
        w0p[(e0 / NI) * W0S + (e0 % NI)] = w0v;
        w0p[(e1 / NI) * W0S + (e1 % NI)] = w0v2;
        w0p[(e2 / NI) * W0S + (e2 % NI)] = w0v3;
    }

    __syncthreads();

    // ---- Stage 2: thread = (m-pair, i), i lane-fast; 252 threads ----
    // outputs t4[m0][i], t4[m0+1][i]; window union xs[j][m0..m0+7] (x cols m0-3..m0+4)
    if (t < 28 * NI) {
        const int i  = t % NI;
        const int m0 = 2 * (t / NI);
        const float* wrow = &w1t[i * W1TS];

        float accA0 = 0.f, accA1 = 0.f;   // output m0
        float accB0 = 0.f, accB1 = 0.f;   // output m0+1

        #pragma unroll
        for (int j = 0; j < NCH; ++j) {
            const float* xb = &xs[j * XSTRIDE + m0];   // even index -> 8B aligned
            float2 f0 = *(const float2*)&xb[0];
            float2 f1 = *(const float2*)&xb[2];
            float2 f2 = *(const float2*)&xb[4];
            float2 f3 = *(const float2*)&xb[6];
            const float xw[8] = {f0.x, f0.y, f1.x, f1.y, f2.x, f2.y, f3.x, f3.y};
            const float* wj = &wrow[j * KS];

            #pragma unroll
            for (int k = 0; k < KS; ++k) {
                const float wv = wj[k];
                if (k & 1) {
                    accA1 = fmaf(xw[k],     wv, accA1);
                    accB1 = fmaf(xw[k + 1], wv, accB1);
                } else {
                    accA0 = fmaf(xw[k],     wv, accA0);
                    accB0 = fmaf(xw[k + 1], wv, accB0);
                }
            }
        }
        *(float2*)&t4s[i * T4S + m0] = make_float2(accA0 + accA1, accB0 + accB1);
    }

    __syncthreads();

    // ---- Stage 3: item = (mq, p); 672 items; vector loads + float4 store ----
    for (int item = t; item < 14 * NP; item += THREADS) {
        const int mq = item / NP;         // warp-uniform -> t4 float4 reads broadcast
        const int p  = item % NP;
        const int m0 = 4 * mq;

        float4 wa = *(const float4*)&w0p[p * W0S + 0];
        float4 wb = *(const float4*)&w0p[p * W0S + 4];
        float  w8 = w0p[p * W0S + 8];
        const float wscal[9] = {wa.x, wa.y, wa.z, wa.w, wb.x, wb.y, wb.z, wb.w, w8};

        float4 r = make_float4(0.f, 0.f, 0.f, 0.f);
        float* rp = (float*)&r;
        #pragma unroll
        for (int i = 0; i < NI; ++i) {
            float4 tq = *(const float4*)&t4s[i * T4S + m0];
            rp[0] = fmaf(tq.x, wscal[i], rp[0]);
            rp[1] = fmaf(tq.y, wscal[i], rp[1]);
            rp[2] = fmaf(tq.z, wscal[i], rp[2]);
            rp[3] = fmaf(tq.w, wscal[i], rp[3]);
        }
        *(float4*)&out[(((o * NP + p) * WID + n) * WID) + m0] = r;
    }
}

extern "C" void kernel_launch(void* const* d_in, const int* in_sizes, int n_in,
                              void* d_out, int out_size) {
    // Bind inputs by size: x=75264, W0=432, W1=756
    const float* x  = (const float*)d_in[0];
    const float* W0 = (const float*)d_in[1];
    const float* W1 = (const float*)d_in[2];
    for (int i = 0; i < n_in; ++i) {
        if (in_sizes[i] == 75264) x  = (const float*)d_in[i];
        else if (in_sizes[i] == 432) W0 = (const float*)d_in[i];
        else if (in_sizes[i] == 756) W1 = (const float*)d_in[i];
    }
    float* out = (float*)d_out;

    fused_sepconv_kernel<<<2 * WID, THREADS>>>(x, W0, W1, out);
}